// round 2
// baseline (speedup 1.0000x reference)
#include <cuda_runtime.h>
#include <cstdint>

#define CHAR_EMB 30
#define NFILT    30
#define MAXW     40
#define NCHARS   102
#define P        4                       // positions per block
#define TH       (P * CHAR_EMB * 2)      // 240 threads: (pos, e, half)

typedef unsigned long long ull;

// ---------- packed f32x2 helpers (sm_103a) ----------
__device__ __forceinline__ ull pk2(float lo, float hi) {
    ull r;
    asm("mov.b64 %0, {%1, %2};" : "=l"(r) : "f"(lo), "f"(hi));
    return r;
}
__device__ __forceinline__ void upk2(float& lo, float& hi, ull v) {
    asm("mov.b64 {%0, %1}, %2;" : "=f"(lo), "=f"(hi) : "l"(v));
}
__device__ __forceinline__ ull fma2(ull a, ull b, ull c) {
    ull d;
    asm("fma.rn.f32x2 %0, %1, %2, %3;" : "=l"(d) : "l"(a), "l"(b), "l"(c));
    return d;
}
__device__ __forceinline__ ull mul2(ull a, ull b) {
    ull d;
    asm("mul.rn.f32x2 %0, %1, %2;" : "=l"(d) : "l"(a), "l"(b));
    return d;
}

// Fused encoder: depthwise conv (30 groups x 30 filters, K=3) + max-over-time
// + glove gather. One thread = (position, group e, time-half h). Each half
// covers 20 conv outputs (2 overlap, harmless for max), combined via shfl.
__global__ __launch_bounds__(TH, 3)
void encoder_kernel(const int*    __restrict__ char_ids,
                    const int*    __restrict__ word_ids,
                    const float*  __restrict__ char_emb,
                    const float*  __restrict__ conv_w,
                    const float*  __restrict__ conv_b,
                    const float4* __restrict__ glove4,
                    float*        __restrict__ out,
                    int n_pos)
{
    __shared__ float emb_s[NCHARS * 32];   // [char][e], padded row 32
    __shared__ float w_s[900 * 4];         // [o] -> (w0,w1,w2,bias)
    __shared__ int   ids_s[P * MAXW];

    const int tid = threadIdx.x;
    const int pos_base = blockIdx.x * P;

    // Glove gather for this block's positions (independent of smem/conv).
    if (tid < P * 25) {
        int gp = pos_base + tid / 25;
        if (gp < n_pos) {
            int j   = tid % 25;
            int wid = word_ids[gp];
            reinterpret_cast<float4*>(out)[(size_t)gp * 250 + 225 + j] =
                glove4[(size_t)wid * 25 + j];
        }
    }

    for (int i = tid; i < NCHARS * CHAR_EMB; i += TH)
        emb_s[(i / CHAR_EMB) * 32 + (i % CHAR_EMB)] = char_emb[i];
    for (int i = tid; i < 900 * 3; i += TH)
        w_s[(i / 3) * 4 + (i % 3)] = conv_w[i];
    for (int i = tid; i < 900; i += TH)
        w_s[i * 4 + 3] = conv_b[i];
    for (int i = tid; i < P * MAXW; i += TH) {
        int g = pos_base * MAXW + i;
        ids_s[i] = (g < n_pos * MAXW) ? char_ids[g] : 0;
    }
    __syncthreads();

    const int pl = tid / (CHAR_EMB * 2);
    const int r  = tid % (CHAR_EMB * 2);
    const int e  = r >> 1;
    const int h  = r & 1;
    const int pos   = pos_base + pl;
    const bool valid = (pos < n_pos);

    // Gather x[tb .. tb+21] for this (pos, e). h0: t 0..21, h1: t 18..39.
    // Both halves run identical instruction sequences (no divergence).
    const int tb = h * 18;
    float xv[22];
#pragma unroll
    for (int j = 0; j < 22; j++)
        xv[j] = emb_s[ids_s[pl * MAXW + tb + j] * 32 + e];

    // Even-phase pairs and odd-phase pairs for packed conv.
    ull xe[11], xo[10];
#pragma unroll
    for (int i = 0; i < 11; i++) xe[i] = pk2(xv[2 * i], xv[2 * i + 1]);
#pragma unroll
    for (int i = 0; i < 10; i++) xo[i] = pk2(xv[2 * i + 1], xv[2 * i + 2]);

    float* outp = out + (size_t)pos * 1000 + e * NFILT;
    const float4* wrow = reinterpret_cast<const float4*>(w_s) + e * NFILT;

#pragma unroll 1
    for (int f = 0; f < NFILT; f++) {
        const float4 w = wrow[f];
        const ull w0 = pk2(w.x, w.x);
        const ull w1 = pk2(w.y, w.y);
        const ull w2 = pk2(w.z, w.z);
        float m0 = -3.402823466e+38f, m1 = -3.402823466e+38f;
#pragma unroll
        for (int tp = 0; tp < 10; tp++) {
            // y[tb+2tp], y[tb+2tp+1]
            ull acc = mul2(w2, xe[tp + 1]);
            acc = fma2(w1, xo[tp], acc);
            acc = fma2(w0, xe[tp], acc);
            float lo, hi;
            upk2(lo, hi, acc);
            m0 = fmaxf(m0, lo);
            m1 = fmaxf(m1, hi);
        }
        float m = fmaxf(m0, m1);
        // Combine the two time-halves (lanes tid, tid^1 — always same warp).
        m = fmaxf(m, __shfl_xor_sync(0xFFFFFFFFu, m, 1));
        if (valid && h == 0)
            outp[f] = m + w.w;
    }
}

extern "C" void kernel_launch(void* const* d_in, const int* in_sizes, int n_in,
                              void* d_out, int out_size)
{
    const int*   char_ids = (const int*)d_in[0];
    const int*   word_ids = (const int*)d_in[1];
    const float* char_emb = (const float*)d_in[2];
    const float* conv_w   = (const float*)d_in[3];
    const float* conv_b   = (const float*)d_in[4];
    const float* glove    = (const float*)d_in[5];
    float*       out      = (float*)d_out;

    const int n_pos = in_sizes[1];   // B*S

    int blocks = (n_pos + P - 1) / P;
    encoder_kernel<<<blocks, TH>>>(char_ids, word_ids, char_emb, conv_w, conv_b,
                                   (const float4*)glove, out, n_pos);
}

// round 3
// speedup vs baseline: 1.1293x; 1.1293x over previous
#include <cuda_runtime.h>
#include <cstdint>

#define CHAR_EMB 30
#define NFILT    30
#define MAXW     40
#define TH       320          // 300 compute threads + 20 glove threads
#define FPT      3            // filters per thread
#define TPG      10           // threads per group (30 filters / 3)

typedef unsigned long long ull;

__device__ __forceinline__ ull pk2(float lo, float hi) {
    ull r;
    asm("mov.b64 %0, {%1, %2};" : "=l"(r) : "f"(lo), "f"(hi));
    return r;
}
__device__ __forceinline__ void upk2(float& lo, float& hi, ull v) {
    asm("mov.b64 {%0, %1}, %2;" : "=f"(lo), "=f"(hi) : "l"(v));
}
__device__ __forceinline__ ull fma2(ull a, ull b, ull c) {
    ull d;
    asm("fma.rn.f32x2 %0, %1, %2, %3;" : "=l"(d) : "l"(a), "l"(b), "l"(c));
    return d;
}
__device__ __forceinline__ ull mul2(ull a, ull b) {
    ull d;
    asm("mul.rn.f32x2 %0, %1, %2;" : "=l"(d) : "l"(a), "l"(b));
    return d;
}

// One block = one sequence position. Gathers the 30x40 char-emb tile into
// smem (even-phase copy A + one-shifted copy B so both conv phases are
// 8B-aligned LDS.64), then 300 threads each compute 3 output filters of one
// group by streaming x pairs from smem. Glove gather rides on 20 pad threads.
__global__ __launch_bounds__(TH, 4)
void encoder_kernel(const int*    __restrict__ char_ids,
                    const int*    __restrict__ word_ids,
                    const float*  __restrict__ char_emb,
                    const float*  __restrict__ conv_w,
                    const float*  __restrict__ conv_b,
                    const float4* __restrict__ glove4,
                    float*        __restrict__ out)
{
    __shared__ float xA[CHAR_EMB * 42];   // x[e][t], row stride 42
    __shared__ float xB[CHAR_EMB * 40];   // x[e][t+1], row stride 40

    const int tid = threadIdx.x;
    const int pos = blockIdx.x;

    // Glove gather: out[pos, 900:1000] = glove[word_ids[pos]]
    if (tid >= 300) {
        const int wid = word_ids[pos];
        for (int j = tid - 300; j < 25; j += 20)
            reinterpret_cast<float4*>(out)[(size_t)pos * 250 + 225 + j] =
                glove4[(size_t)wid * 25 + j];
    }

    // Gather char-emb tile: 1200 values, coalesced over e.
    for (int v = tid; v < CHAR_EMB * MAXW; v += TH) {
        const int t = v / CHAR_EMB;
        const int e = v % CHAR_EMB;
        const int id = char_ids[pos * MAXW + t];
        const float val = char_emb[id * CHAR_EMB + e];
        xA[e * 42 + t] = val;
        if (t >= 1 && t <= 38) xB[e * 40 + (t - 1)] = val;
    }
    __syncthreads();

    if (tid >= 300) return;

    const int e  = tid / TPG;
    const int f0 = (tid % TPG) * FPT;
    const int oc = e * NFILT + f0;

    // Load 3 filters' weights (L1-resident tables), pack broadcast pairs.
    ull w0[FPT], w1[FPT], w2[FPT];
    float bias[FPT];
#pragma unroll
    for (int f = 0; f < FPT; f++) {
        const float* wp = conv_w + (size_t)(oc + f) * 3;
        w0[f] = pk2(wp[0], wp[0]);
        w1[f] = pk2(wp[1], wp[1]);
        w2[f] = pk2(wp[2], wp[2]);
        bias[f] = conv_b[oc + f];
    }

    const float2* pa = reinterpret_cast<const float2*>(xA + e * 42);
    const float2* pb = reinterpret_cast<const float2*>(xB + e * 40);

    float m0[FPT], m1[FPT];
#pragma unroll
    for (int f = 0; f < FPT; f++) { m0[f] = -3.402823466e+38f; m1[f] = m0[f]; }

    float2 av = pa[0];
    ull a = pk2(av.x, av.y);
#pragma unroll
    for (int i = 0; i < 19; i++) {
        const float2 anv = pa[i + 1];
        const float2 bv  = pb[i];
        const ull an = pk2(anv.x, anv.y);
        const ull b  = pk2(bv.x, bv.y);
#pragma unroll
        for (int f = 0; f < FPT; f++) {
            // y[2i], y[2i+1] = w0*x[2i..] + w1*x[2i+1..] + w2*x[2i+2..]
            ull acc = mul2(w2[f], an);
            acc = fma2(w1[f], b, acc);
            acc = fma2(w0[f], a, acc);
            float lo, hi;
            upk2(lo, hi, acc);
            m0[f] = fmaxf(m0[f], lo);
            m1[f] = fmaxf(m1[f], hi);
        }
        a = an;
    }

    float* outp = out + (size_t)pos * 1000 + oc;
#pragma unroll
    for (int f = 0; f < FPT; f++)
        outp[f] = fmaxf(m0[f], m1[f]) + bias[f];
}

extern "C" void kernel_launch(void* const* d_in, const int* in_sizes, int n_in,
                              void* d_out, int out_size)
{
    const int*   char_ids = (const int*)d_in[0];
    const int*   word_ids = (const int*)d_in[1];
    const float* char_emb = (const float*)d_in[2];
    const float* conv_w   = (const float*)d_in[3];
    const float* conv_b   = (const float*)d_in[4];
    const float* glove    = (const float*)d_in[5];
    float*       out      = (float*)d_out;

    const int n_pos = in_sizes[1];   // B*S

    encoder_kernel<<<n_pos, TH>>>(char_ids, word_ids, char_emb, conv_w, conv_b,
                                  (const float4*)glove, out);
}

// round 4
// speedup vs baseline: 1.1647x; 1.0314x over previous
#include <cuda_runtime.h>
#include <cstdint>

#define CHAR_EMB 30
#define NFILT    30
#define MAXW     40
#define TH       320        // 300 compute + 20 glove threads
#define FPT      3          // filters per thread
#define TPG      10         // threads per group
#define STRA     42         // xA row stride (floats), 21 ull
#define STRB     40         // xB row stride (floats), 20 ull
#define NVAL     (CHAR_EMB * MAXW)   // 1200

typedef unsigned long long ull;

__device__ __forceinline__ ull pk2(float lo, float hi) {
    ull r;
    asm("mov.b64 %0, {%1, %2};" : "=l"(r) : "f"(lo), "f"(hi));
    return r;
}
__device__ __forceinline__ void upk2(float& lo, float& hi, ull v) {
    asm("mov.b64 {%0, %1}, %2;" : "=f"(lo), "=f"(hi) : "l"(v));
}
__device__ __forceinline__ ull fma2(ull a, ull b, ull c) {
    ull d;
    asm("fma.rn.f32x2 %0, %1, %2, %3;" : "=l"(d) : "l"(a), "l"(b), "l"(c));
    return d;
}
__device__ __forceinline__ ull mul2(ull a, ull b) {
    ull d;
    asm("mul.rn.f32x2 %0, %1, %2;" : "=l"(d) : "l"(a), "l"(b));
    return d;
}

// Persistent-ish blocks: each block walks positions bid, bid+grid, ... with a
// 2-deep software pipeline (smem double buffer). Compute(p) overlaps the
// char-emb gather for p+1 and the id loads for p+2. Weights live in registers
// for the whole block lifetime.
__global__ __launch_bounds__(TH, 4)
void encoder_kernel(const int*    __restrict__ char_ids,
                    const int*    __restrict__ word_ids,
                    const float*  __restrict__ char_emb,
                    const float*  __restrict__ conv_w,
                    const float*  __restrict__ conv_b,
                    const float4* __restrict__ glove4,
                    float*        __restrict__ out,
                    int n_pos)
{
    __shared__ __align__(16) float xA[2][CHAR_EMB * STRA]; // x[e][t],   t=0..39
    __shared__ __align__(16) float xB[2][CHAR_EMB * STRB]; // x[e][t+1], shifted copy
    __shared__ int ids_s[2][MAXW];

    const int tid    = threadIdx.x;
    const int pos0   = blockIdx.x;
    const int stride = gridDim.x;
    if (pos0 >= n_pos) return;

    // ---- persistent per-thread weights (compute threads only) ----
    const int e  = (tid < 300) ? tid / TPG : 0;
    const int f0 = (tid < 300) ? (tid % TPG) * FPT : 0;
    const int oc = e * NFILT + f0;
    ull w0[FPT], w1[FPT], w2[FPT];
    float bias[FPT];
#pragma unroll
    for (int f = 0; f < FPT; f++) {
        const float* wp = conv_w + (size_t)(oc + f) * 3;
        w0[f] = pk2(wp[0], wp[0]);
        w1[f] = pk2(wp[1], wp[1]);
        w2[f] = pk2(wp[2], wp[2]);
        bias[f] = conv_b[oc + f];
    }

    // ---- prologue: fill buffer 0 with emb(pos0); stage ids(pos0+stride) ----
    if (tid < MAXW) ids_s[0][tid] = char_ids[pos0 * MAXW + tid];
    __syncthreads();

    float r[4];
#pragma unroll
    for (int j = 0; j < 4; j++) {
        const int v = tid + j * TH;
        if (v < NVAL)
            r[j] = char_emb[ids_s[0][v / CHAR_EMB] * CHAR_EMB + (v % CHAR_EMB)];
    }
    int idreg = 0;
    const int pos1 = pos0 + stride;
    if (tid < MAXW && pos1 < n_pos) idreg = char_ids[pos1 * MAXW + tid];
#pragma unroll
    for (int j = 0; j < 4; j++) {
        const int v = tid + j * TH;
        if (v < NVAL) {
            const int t = v / CHAR_EMB, e2 = v % CHAR_EMB;
            xA[0][e2 * STRA + t] = r[j];
            if (t >= 1 && t <= 38) xB[0][e2 * STRB + (t - 1)] = r[j];
        }
    }
    if (tid < MAXW && pos1 < n_pos) ids_s[1][tid] = idreg;
    __syncthreads();

    // ---- main pipelined loop ----
    int k = 0;
    for (int p = pos0; p < n_pos; p += stride, k ^= 1) {
        const int nxt = p + stride;

        // prefetch emb(nxt) using already-staged ids; independent LDGs.
        if (nxt < n_pos) {
#pragma unroll
            for (int j = 0; j < 4; j++) {
                const int v = tid + j * TH;
                if (v < NVAL)
                    r[j] = char_emb[ids_s[k ^ 1][v / CHAR_EMB] * CHAR_EMB + (v % CHAR_EMB)];
            }
        }
        // prefetch ids(nxt + stride)
        int idreg2 = 0;
        if (tid < MAXW && nxt + stride < n_pos)
            idreg2 = char_ids[(nxt + stride) * MAXW + tid];

        if (tid >= 300) {
            // glove gather rides on the 20 spare threads
            const int wid = word_ids[p];
#pragma unroll
            for (int j = tid - 300; j < 25; j += 20)
                reinterpret_cast<float4*>(out)[(size_t)p * 250 + 225 + j] =
                    glove4[(size_t)wid * 25 + j];
        } else {
            // conv + max-over-time for (p, e), 3 filters
            const ull* A = reinterpret_cast<const ull*>(xA[k]) + e * (STRA / 2);
            const ull* B = reinterpret_cast<const ull*>(xB[k]) + e * (STRB / 2);
            float m0[FPT], m1[FPT];
#pragma unroll
            for (int f = 0; f < FPT; f++) { m0[f] = -3.402823466e+38f; m1[f] = m0[f]; }

            ull a = A[0];
#pragma unroll
            for (int i = 0; i < 19; i++) {
                const ull an = A[i + 1];
                const ull b  = B[i];
#pragma unroll
                for (int f = 0; f < FPT; f++) {
                    ull acc = mul2(w2[f], an);
                    acc = fma2(w1[f], b, acc);
                    acc = fma2(w0[f], a, acc);
                    float lo, hi;
                    upk2(lo, hi, acc);
                    m0[f] = fmaxf(m0[f], lo);
                    m1[f] = fmaxf(m1[f], hi);
                }
                a = an;
            }
            float* outp = out + (size_t)p * 1000 + oc;
#pragma unroll
            for (int f = 0; f < FPT; f++)
                outp[f] = fmaxf(m0[f], m1[f]) + bias[f];
        }

        // stage next position into the other buffer
        if (nxt < n_pos) {
#pragma unroll
            for (int j = 0; j < 4; j++) {
                const int v = tid + j * TH;
                if (v < NVAL) {
                    const int t = v / CHAR_EMB, e2 = v % CHAR_EMB;
                    xA[k ^ 1][e2 * STRA + t] = r[j];
                    if (t >= 1 && t <= 38) xB[k ^ 1][e2 * STRB + (t - 1)] = r[j];
                }
            }
            if (tid < MAXW && nxt + stride < n_pos) ids_s[k][tid] = idreg2;
            __syncthreads();
        }
    }
}

extern "C" void kernel_launch(void* const* d_in, const int* in_sizes, int n_in,
                              void* d_out, int out_size)
{
    const int*   char_ids = (const int*)d_in[0];
    const int*   word_ids = (const int*)d_in[1];
    const float* char_emb = (const float*)d_in[2];
    const float* conv_w   = (const float*)d_in[3];
    const float* conv_b   = (const float*)d_in[4];
    const float* glove    = (const float*)d_in[5];
    float*       out      = (float*)d_out;

    const int n_pos = in_sizes[1];   // B*S

    int blocks = 608;                 // 4 per SM on 152-SM GB300
    if (blocks > n_pos) blocks = n_pos;
    encoder_kernel<<<blocks, TH>>>(char_ids, word_ids, char_emb, conv_w, conv_b,
                                   (const float4*)glove, out, n_pos);
}